// round 1
// baseline (speedup 1.0000x reference)
#include <cuda_runtime.h>

#define N_NODES 50000
#define N_EDGES 1600000
#define NCLS    48
#define NSTEP   10
#define SCAN_B  1024
#define NBLK    ((N_NODES + SCAN_B - 1) / SCAN_B)   // 49

// ---------------- device scratch (static, no runtime allocation) -------------
__device__ float g_deg[N_NODES];
__device__ int   g_cnt[N_NODES];
__device__ int   g_off[N_NODES + 1];
__device__ int   g_cur[N_NODES];
__device__ int   g_src[N_EDGES];
__device__ float g_wgt[N_EDGES];
__device__ float g_h[2][(size_t)N_NODES * NCLS];
__device__ int   g_bsums[64];

// ---------------- preprocessing kernels --------------------------------------
__global__ void zero_kernel() {
    int i = blockIdx.x * blockDim.x + threadIdx.x;
    if (i < N_NODES) { g_deg[i] = 0.0f; g_cnt[i] = 0; }
}

__global__ void deg_kernel(const int* __restrict__ row, const int* __restrict__ col,
                           const float* __restrict__ attr) {
    int e = blockIdx.x * blockDim.x + threadIdx.x;
    if (e < N_EDGES) {
        atomicAdd(&g_deg[row[e]], attr[e]);
        atomicAdd(&g_cnt[col[e]], 1);
    }
}

// per-block inclusive scan -> exclusive local + block sums
__global__ void scan1_kernel() {
    __shared__ int sh[SCAN_B];
    int tid = threadIdx.x;
    int i = blockIdx.x * SCAN_B + tid;
    int v = (i < N_NODES) ? g_cnt[i] : 0;
    sh[tid] = v;
    __syncthreads();
    for (int d = 1; d < SCAN_B; d <<= 1) {
        int t = (tid >= d) ? sh[tid - d] : 0;
        __syncthreads();
        sh[tid] += t;
        __syncthreads();
    }
    if (i < N_NODES) g_off[i] = sh[tid] - v;   // exclusive within block
    if (tid == SCAN_B - 1) g_bsums[blockIdx.x] = sh[tid];
}

// exclusive scan of the 49 block sums (single block of 64 threads)
__global__ void scan2_kernel() {
    __shared__ int sh[64];
    int tid = threadIdx.x;
    int v = (tid < NBLK) ? g_bsums[tid] : 0;
    sh[tid] = v;
    __syncthreads();
    for (int d = 1; d < 64; d <<= 1) {
        int t = (tid >= d) ? sh[tid - d] : 0;
        __syncthreads();
        sh[tid] += t;
        __syncthreads();
    }
    if (tid < NBLK) g_bsums[tid] = sh[tid] - v;
}

// add block offsets, copy cursor, finalize off[N]
__global__ void scan3_kernel() {
    int i = blockIdx.x * blockDim.x + threadIdx.x;
    if (i < N_NODES) {
        int o = g_off[i] + g_bsums[i / SCAN_B];
        g_off[i] = o;
        g_cur[i] = o;
    }
    if (i == 0) g_off[N_NODES] = N_EDGES;
}

// bucket edges by destination; precompute row-normalized weight
__global__ void fill_kernel(const int* __restrict__ row, const int* __restrict__ col,
                            const float* __restrict__ attr) {
    int e = blockIdx.x * blockDim.x + threadIdx.x;
    if (e < N_EDGES) {
        int r = row[e];
        int c = col[e];
        int p = atomicAdd(&g_cur[c], 1);
        g_src[p] = r;
        g_wgt[p] = attr[e] / fmaxf(g_deg[r], 1e-12f);
    }
}

// one-hot init into g_h[0]
__global__ void h0_kernel(const int* __restrict__ target) {
    int idx = blockIdx.x * blockDim.x + threadIdx.x;
    if (idx < N_NODES * NCLS) {
        int n = idx / NCLS;
        int c = idx - n * NCLS;
        g_h[0][idx] = (target[n] == c) ? 1.0f : 0.0f;
    }
}

// ---------------- main propagation step: one warp per destination node -------
// h_new[n] = sum_{e in in(n)} w[e] * h_old[src[e]];  out[n] += h_new[n] * W[:,s]
__global__ void gather_kernel(const float* __restrict__ Wm, float* __restrict__ out, int s) {
    int gwarp = (blockIdx.x * blockDim.x + threadIdx.x) >> 5;
    int lane  = threadIdx.x & 31;
    if (gwarp >= N_NODES) return;

    const float* __restrict__ hin  = g_h[s & 1];
    float*       __restrict__ hout = g_h[(s & 1) ^ 1];

    int beg = g_off[gwarp];
    int end = g_off[gwarp + 1];

    float a0 = 0.f, a1 = 0.f, a2 = 0.f, a3 = 0.f;   // classes [0,32)
    float b0 = 0.f, b1 = 0.f, b2 = 0.f, b3 = 0.f;   // classes [32,48)
    bool hi = (lane < 16);

    int j = beg;
    for (; j + 4 <= end; j += 4) {
        int   s0 = g_src[j],     s1 = g_src[j + 1], s2 = g_src[j + 2], s3 = g_src[j + 3];
        float w0 = g_wgt[j],     w1 = g_wgt[j + 1], w2 = g_wgt[j + 2], w3 = g_wgt[j + 3];
        const float* r0 = hin + (size_t)s0 * NCLS;
        const float* r1 = hin + (size_t)s1 * NCLS;
        const float* r2 = hin + (size_t)s2 * NCLS;
        const float* r3 = hin + (size_t)s3 * NCLS;
        float x0 = r0[lane], x1 = r1[lane], x2 = r2[lane], x3 = r3[lane];
        float y0 = 0.f, y1 = 0.f, y2 = 0.f, y3 = 0.f;
        if (hi) { y0 = r0[32 + lane]; y1 = r1[32 + lane]; y2 = r2[32 + lane]; y3 = r3[32 + lane]; }
        a0 = fmaf(w0, x0, a0); a1 = fmaf(w1, x1, a1);
        a2 = fmaf(w2, x2, a2); a3 = fmaf(w3, x3, a3);
        b0 = fmaf(w0, y0, b0); b1 = fmaf(w1, y1, b1);
        b2 = fmaf(w2, y2, b2); b3 = fmaf(w3, y3, b3);
    }
    for (; j < end; j++) {
        int   sv = g_src[j];
        float wv = g_wgt[j];
        const float* r = hin + (size_t)sv * NCLS;
        a0 = fmaf(wv, r[lane], a0);
        if (hi) b0 = fmaf(wv, r[32 + lane], b0);
    }
    float acc0 = (a0 + a1) + (a2 + a3);
    float acc1 = (b0 + b1) + (b2 + b3);

    float* hrow = hout + (size_t)gwarp * NCLS;
    float* orow = out  + (size_t)gwarp * NCLS;

    hrow[lane] = acc0;
    float o0 = acc0 * Wm[lane * NSTEP + s];
    if (s != 0) o0 += orow[lane];
    orow[lane] = o0;

    if (hi) {
        hrow[32 + lane] = acc1;
        float o1 = acc1 * Wm[(32 + lane) * NSTEP + s];
        if (s != 0) o1 += orow[32 + lane];
        orow[32 + lane] = o1;
    }
}

// ---------------- launch ------------------------------------------------------
extern "C" void kernel_launch(void* const* d_in, const int* in_sizes, int n_in,
                              void* d_out, int out_size) {
    const int*   ei     = (const int*)d_in[0];     // [2, E]
    const int*   row    = ei;
    const int*   col    = ei + N_EDGES;
    const float* attr   = (const float*)d_in[1];   // [E]
    const int*   target = (const int*)d_in[2];     // [N]
    const float* Wm     = (const float*)d_in[3];   // [C, S]
    float*       out    = (float*)d_out;           // [N, C]

    const int TB = 256;
    int nblk_nodes = (N_NODES + TB - 1) / TB;
    int nblk_edges = (N_EDGES + TB - 1) / TB;
    int nblk_nc    = (N_NODES * NCLS + TB - 1) / TB;

    zero_kernel<<<nblk_nodes, TB>>>();
    deg_kernel<<<nblk_edges, TB>>>(row, col, attr);
    scan1_kernel<<<NBLK, SCAN_B>>>();
    scan2_kernel<<<1, 64>>>();
    scan3_kernel<<<nblk_nodes, TB>>>();
    fill_kernel<<<nblk_edges, TB>>>(row, col, attr);
    h0_kernel<<<nblk_nc, TB>>>(target);

    // one warp per node: 8 warps / 256-thread block
    int nblk_gather = (N_NODES + 7) / 8;
    for (int s = 0; s < NSTEP; s++) {
        gather_kernel<<<nblk_gather, TB>>>(Wm, out, s);
    }
}